// round 16
// baseline (speedup 1.0000x reference)
#include <cuda_runtime.h>
#include <cstdint>

// EdgeModel: out[e,:] = relu([src,dest,attr,u[batch]] @ W1 + b1) @ W2 + b2
// E = 8e6, B = 4096, W1:(4,10), W2:(10,19). Output [E,19] f32.
//
// R15 = R14 (138.8us, const-port ~77us just under the kernel) + port split.
// At 4 edges/thread the split finally pays (it couldn't at 2 edges, R11):
//  - layer-1 weights stay in __constant__: 50 LDC/warp -> ~23us const port.
//  - layer-2 weights/biases staged to smem: ~114 LDS/warp at floor-2 ->
//    ~37us on the L1 port (incl. STS + LDG wavefronts).
// Both ports now sit far below the ~100us DRAM stream -> DRAM becomes the
// sole binding resource. smem 38.9 -> 40.6KB (still 5 CTAs/SM).
// Everything else identical to R14: TPB=128, 4 edges/thread (2 packed
// pairs), 512-edge tile, single block TMA bulk store, carry-paired
// conflict-free float2 tile stores, fused prep kernel.

#define TPB 128
#define EDGES_PER_BLOCK 512   // TPB * 4
#define TILE_BYTES 38912      // 512 * 19 * 4
#define HALF_ROWS (EDGES_PER_BLOCK / 2 * 19)   // float offset of pair-B half

typedef unsigned long long u64;

__device__ int g_batch_is64;   // 1 if batch is int64, 0 if int32

struct CWPack {
    u64 w1p[40];    // {W1[c][k]}x2, index c*10+k
    u64 b1p[10];    // {b1[k]}x2
    u64 w2p[190];   // {W2[k][j]}x2 transposed, index j*10+k  (16B-aligned rows)
    u64 b2p[19];    // {b2[j]}x2
    u64 pad;
};

__device__ CWPack g_wscratch;      // staging (written by prep kernel)
__constant__ CWPack c_w;           // read-only broadcast copy

__device__ __forceinline__ u64 pack2(float lo, float hi) {
    u64 r;
    asm("mov.b64 %0, {%1, %2};" : "=l"(r) : "f"(lo), "f"(hi));
    return r;
}

__device__ __forceinline__ void unpack2(u64 v, float& lo, float& hi) {
    asm("mov.b64 {%0, %1}, %2;" : "=f"(lo), "=f"(hi) : "l"(v));
}

__device__ __forceinline__ u64 fma2(u64 a, u64 b, u64 c) {
    u64 d;
    asm("fma.rn.f32x2 %0, %1, %2, %3;" : "=l"(d) : "l"(a), "l"(b), "l"(c));
    return d;
}

__device__ __forceinline__ u64 relu2(u64 v) {
    float lo, hi;
    unpack2(v, lo, hi);
    lo = fmaxf(lo, 0.0f);
    hi = fmaxf(hi, 0.0f);
    return pack2(lo, hi);
}

// Build weight pack + detect batch dtype (int64 values 0..4095 -> all odd
// int32 words zero; 1024 random int32 in [0,4096) all-zero: impossible).
__global__ void prep_weights(const float* __restrict__ W1,
                             const float* __restrict__ b1,
                             const float* __restrict__ W2,
                             const float* __restrict__ b2,
                             const int*   __restrict__ b32)
{
    int t = threadIdx.x;
    if (t < 40)             g_wscratch.w1p[t]      = pack2(W1[t], W1[t]);
    if (t >= 64 && t < 74)  g_wscratch.b1p[t - 64] = pack2(b1[t - 64], b1[t - 64]);
    if (t >= 96 && t < 115) g_wscratch.b2p[t - 96] = pack2(b2[t - 96], b2[t - 96]);
    if (t < 190) {
        int j = t / 10, k = t - j * 10;   // transpose
        float w = W2[k * 19 + j];
        g_wscratch.w2p[t] = pack2(w, w);
    }
    if (t == 255) g_wscratch.pad = 0;

    if (t >= 192 && t < 224) {            // warp 6: parallel dtype scan
        int lane = t - 192;
        int bad = 0;
        #pragma unroll 4
        for (int i = 0; i < 32; i++)
            bad |= b32[1 + 2 * (lane * 32 + i)];
        unsigned any = __ballot_sync(0xffffffffu, bad != 0);
        if (lane == 0) g_batch_is64 = (any == 0) ? 1 : 0;
    }
}

__global__ __launch_bounds__(TPB, 5)
void edge_model_kernel(const float* __restrict__ src,
                       const float* __restrict__ dest,
                       const float* __restrict__ ea,
                       const float* __restrict__ u,
                       const void*  __restrict__ batch_raw,
                       float* __restrict__ out,        // [E,19]
                       long long E)
{
    __shared__ __align__(16) float otile[EDGES_PER_BLOCK * 19];  // 38912 B
    __shared__ __align__(16) u64 w2s[190];   // layer-2 weights on the L1 port
    __shared__ u64 b2s[19];

    const int t = threadIdx.x;
    const int is64 = g_batch_is64;

    // Stage layer-2 weights const->smem once per block.
    if (t < 128) {
        w2s[t] = c_w.w2p[t];
        if (t < 62) w2s[128 + t] = c_w.w2p[128 + t];
        else if (t < 81) b2s[t - 62] = c_w.b2p[t - 62];
    }
    __syncthreads();

    const long long base = (long long)blockIdx.x * EDGES_PER_BLOCK;

    if (base + EDGES_PER_BLOCK <= E) {
        // ========= fast path: 512-edge block, 4 edges/thread (2 packed pairs) =========
        const long long P = base >> 1;          // first pair of block
        const long long p0 = P + t;             // pair A -> edges 2t, 2t+1
        const long long p1 = P + TPB + t;       // pair B -> edges 256+2t, 256+2t+1

        // Batch indices first (head the dependent batch -> u chain).
        long long i00, i01, i10, i11;
        if (is64) {
            longlong2 q0 = ((const longlong2*)batch_raw)[p0];
            longlong2 q1 = ((const longlong2*)batch_raw)[p1];
            i00 = q0.x; i01 = q0.y; i10 = q1.x; i11 = q1.y;
        } else {
            int2 q0 = ((const int2*)batch_raw)[p0];
            int2 q1 = ((const int2*)batch_raw)[p1];
            i00 = q0.x; i01 = q0.y; i10 = q1.x; i11 = q1.y;
        }
        const u64 up0 = pack2(__ldg(&u[i00]), __ldg(&u[i01]));
        const u64 up1 = pack2(__ldg(&u[i10]), __ldg(&u[i11]));

        const float2 s0 = ((const float2*)src)[p0];
        const float2 d0 = ((const float2*)dest)[p0];
        const float2 a0 = ((const float2*)ea)[p0];
        const float2 s1 = ((const float2*)src)[p1];
        const float2 d1 = ((const float2*)dest)[p1];
        const float2 a1 = ((const float2*)ea)[p1];

        const u64 sp0 = pack2(s0.x, s0.y), sp1 = pack2(s1.x, s1.y);
        const u64 dp0 = pack2(d0.x, d0.y), dp1 = pack2(d1.x, d1.y);
        const u64 ap0 = pack2(a0.x, a0.y), ap1 = pack2(a1.x, a1.y);

        // layer 1 for both pairs — const-port weights, every LDC serves 4 edges.
        u64 h0[10], h1[10];
        #pragma unroll
        for (int k = 0; k < 10; k++) {
            const u64 wa = c_w.w1p[k],      wb = c_w.w1p[10 + k];
            const u64 wc = c_w.w1p[20 + k], wd = c_w.w1p[30 + k];
            const u64 bb = c_w.b1p[k];
            u64 acc0 = bb, acc1 = bb;
            acc0 = fma2(sp0, wa, acc0);  acc1 = fma2(sp1, wa, acc1);
            acc0 = fma2(dp0, wb, acc0);  acc1 = fma2(dp1, wb, acc1);
            acc0 = fma2(ap0, wc, acc0);  acc1 = fma2(ap1, wc, acc1);
            acc0 = fma2(up0, wd, acc0);  acc1 = fma2(up1, wd, acc1);
            h0[k] = relu2(acc0);
            h1[k] = relu2(acc1);
        }

        // layer 2: weights via broadcast LDS.128 (L1 port), carry-paired
        // conflict-free float2 tile stores, two pairs.
        float* r0a = &otile[(2 * t)     * 19];
        float* r0b = &otile[(2 * t + 1) * 19];
        float* r1a = &otile[HALF_ROWS + (2 * t)     * 19];
        float* r1b = &otile[HALF_ROWS + (2 * t + 1) * 19];

        u64 prev0, prev1;
        {   // j = 0
            u64 acc0 = b2s[0], acc1 = acc0;
            const ulonglong2* wr = (const ulonglong2*)&w2s[0];
            #pragma unroll
            for (int kk = 0; kk < 5; kk++) {
                ulonglong2 w = wr[kk];
                acc0 = fma2(h0[2 * kk],     w.x, acc0);
                acc0 = fma2(h0[2 * kk + 1], w.y, acc0);
                acc1 = fma2(h1[2 * kk],     w.x, acc1);
                acc1 = fma2(h1[2 * kk + 1], w.y, acc1);
            }
            float lo, hi;
            unpack2(acc0, lo, hi);  r0b[0] = hi;
            unpack2(acc1, lo, hi);  r1b[0] = hi;
            prev0 = acc0;  prev1 = acc1;
        }
        #pragma unroll 2
        for (int j = 1; j < 19; j++) {
            u64 acc0 = b2s[j], acc1 = acc0;
            const ulonglong2* wr = (const ulonglong2*)&w2s[j * 10];  // 16B aligned
            #pragma unroll
            for (int kk = 0; kk < 5; kk++) {
                ulonglong2 w = wr[kk];
                acc0 = fma2(h0[2 * kk],     w.x, acc0);
                acc0 = fma2(h0[2 * kk + 1], w.y, acc0);
                acc1 = fma2(h1[2 * kk],     w.x, acc1);
                acc1 = fma2(h1[2 * kk + 1], w.y, acc1);
            }
            float pl, ph, cl, ch;
            unpack2(prev0, pl, ph);
            unpack2(acc0,  cl, ch);
            if (j & 1) *(float2*)(r0a + j - 1) = make_float2(pl, cl);
            else       *(float2*)(r0b + j - 1) = make_float2(ph, ch);
            unpack2(prev1, pl, ph);
            unpack2(acc1,  cl, ch);
            if (j & 1) *(float2*)(r1a + j - 1) = make_float2(pl, cl);
            else       *(float2*)(r1b + j - 1) = make_float2(ph, ch);
            prev0 = acc0;  prev1 = acc1;
        }
        {   // tails: r0a[18], r1a[18]
            float lo, hi;
            unpack2(prev0, lo, hi);  r0a[18] = lo;
            unpack2(prev1, lo, hi);  r1a[18] = lo;
        }
        __syncthreads();

        // One TMA bulk store flushes the whole tile.
        if (t == 0) {
            unsigned saddr = (unsigned)__cvta_generic_to_shared(otile);
            const float* g = out + base * 19;   // 16B-aligned
            asm volatile("fence.proxy.async.shared::cta;" ::: "memory");
            asm volatile(
                "cp.async.bulk.global.shared::cta.bulk_group [%0], [%1], %2;"
                :: "l"(g), "r"(saddr), "r"((unsigned)TILE_BYTES) : "memory");
            asm volatile("cp.async.bulk.commit_group;" ::: "memory");
            asm volatile("cp.async.bulk.wait_group 0;" ::: "memory");
        }
    } else {
        // ================= tail path (scalar, bounds-checked) =================
        for (long long e = base + t; e < E; e += TPB) {
            float x0 = src[e], x1 = dest[e], x2 = ea[e];
            long long bi = is64 ? ((const long long*)batch_raw)[e]
                                : (long long)((const int*)batch_raw)[e];
            float x3 = u[bi];
            float h[10];
            #pragma unroll
            for (int k = 0; k < 10; k++) {
                float lo, hiu;
                unpack2(c_w.w1p[k], lo, hiu);       float wa = lo;
                unpack2(c_w.w1p[10 + k], lo, hiu);  float wb = lo;
                unpack2(c_w.w1p[20 + k], lo, hiu);  float wc = lo;
                unpack2(c_w.w1p[30 + k], lo, hiu);  float wd = lo;
                unpack2(c_w.b1p[k], lo, hiu);
                float acc = lo;
                acc = fmaf(x0, wa, acc);
                acc = fmaf(x1, wb, acc);
                acc = fmaf(x2, wc, acc);
                acc = fmaf(x3, wd, acc);
                h[k] = fmaxf(acc, 0.0f);
            }
            #pragma unroll
            for (int j = 0; j < 19; j++) {
                float lo, hiu;
                unpack2(c_w.b2p[j], lo, hiu);
                float acc = lo;
                #pragma unroll
                for (int k = 0; k < 10; k++) {
                    unpack2(c_w.w2p[j * 10 + k], lo, hiu);
                    acc = fmaf(h[k], lo, acc);
                }
                out[e * 19 + j] = acc;
            }
        }
    }
}

extern "C" void kernel_launch(void* const* d_in, const int* in_sizes, int n_in,
                              void* d_out, int out_size)
{
    const float* src   = (const float*)d_in[0];
    const float* dest  = (const float*)d_in[1];
    const float* ea    = (const float*)d_in[2];
    const float* u     = (const float*)d_in[3];
    const void*  batch = d_in[4];
    const float* W1    = (const float*)d_in[5];
    const float* b1    = (const float*)d_in[6];
    const float* W2    = (const float*)d_in[7];
    const float* b2    = (const float*)d_in[8];
    float* out = (float*)d_out;

    const long long E = in_sizes[0];
    const int blocks = (int)((E + EDGES_PER_BLOCK - 1) / EDGES_PER_BLOCK);

    prep_weights<<<1, 256>>>(W1, b1, W2, b2, (const int*)batch);

    void* scratch_addr = nullptr;
    cudaGetSymbolAddress(&scratch_addr, g_wscratch);
    cudaMemcpyToSymbolAsync(c_w, scratch_addr, sizeof(CWPack), 0,
                            cudaMemcpyDeviceToDevice, 0);

    edge_model_kernel<<<blocks, TPB>>>(src, dest, ea, u, batch, out, E);
}